// round 6
// baseline (speedup 1.0000x reference)
#include <cuda_runtime.h>
#include <cuda_bf16.h>

// HashingDiscretizer: for each (key, val) pair
//   calibrated (key in feature table, == arange(F) in practice):
//     bin = lower_bound(bin_vals[key*63 .. +63], val) in [0,63]
//     out_key = (((u32)key * GOLDEN + bin) * GOLDEN) & (2^22-1), out_val = 1
//   else: out_key = key & (2^22-1), out_val = val
// Output: float[2*nnz] = [out_keys ; out_vals]  (all values exact in f32)
//
// Input int-dtype (int32 vs int64) is detected at runtime from the byte
// pattern; arange-ness of feature_ids is verified per launch so the hot path
// needs zero feature-table gathers (generic binary-search fallback retained).
//
// Bin search: per-feature 2-level structure (built per launch, ~0 cost):
//   T[0..7]  = {S31,S15,S47,S7,S23,S39,S55,+INF}   (top 3 tree levels, 32B)
//   T[8..71] = S[0..62] padded with +INF            (8 aligned 32B chunks)
// Hot path: 2x LDG.128 (top) -> 3 branchless levels -> chunk p ->
// 2x LDG.128 (chunk) -> bin = 8p + sum(chunk < v). 4 LDGs, 2 sectors/elem.

#define NBIN 63
#define MAX_F 8192
#define OUT_MASK 0x3FFFFFu
#define GOLDEN 0x9E3779B9u

__device__ float4 g_tree[MAX_F * 18];  // 72 floats (18 float4) per feature
__device__ int g_k64;     // 1 if keys buffer is int64
__device__ int g_f64;     // 1 if feature_ids buffer is int64
__device__ int g_arange;  // 1 if feature_ids == arange(F)

__global__ void detect_kernel(const unsigned* __restrict__ keys,
                              const unsigned* __restrict__ fid,
                              int nnz, int F) {
    __shared__ int s_k32, s_f32, s_bad;
    if (threadIdx.x == 0) { s_k32 = 0; s_f32 = 0; s_bad = 0; }
    __syncthreads();
    // dtype sniff: int64 little-endian with small nonneg values => odd u32
    // words all zero. int32 random in-range values => odd words mostly nonzero.
    int lk = 0, lf = 0;
    int nk = min(nnz, 4096);
    for (int i = threadIdx.x; i < nk; i += blockDim.x)
        if (keys[2 * i + 1] != 0u) lk = 1;
    int nf = min(F, 4096);
    for (int i = threadIdx.x; i < nf; i += blockDim.x)
        if (fid[2 * i + 1] != 0u) lf = 1;
    if (lk) atomicOr(&s_k32, 1);
    if (lf) atomicOr(&s_f32, 1);
    __syncthreads();
    int f64 = !s_f32;
    int bad = 0;
    if (f64) {
        const long long* p = (const long long*)fid;
        for (int i = threadIdx.x; i < F; i += blockDim.x)
            if (p[i] != (long long)i) bad = 1;
    } else {
        const int* p = (const int*)fid;
        for (int i = threadIdx.x; i < F; i += blockDim.x)
            if (p[i] != i) bad = 1;
    }
    if (bad) atomicOr(&s_bad, 1);
    __syncthreads();
    if (threadIdx.x == 0) {
        g_k64 = !s_k32;
        g_f64 = f64;
        g_arange = !s_bad;
    }
}

__global__ void build_tree_kernel(const float* __restrict__ bin_vals, int F) {
    int f = blockIdx.x;
    if (f >= F) return;
    int t = threadIdx.x;  // 64 threads
    const float* S = bin_vals + (long long)f * NBIN;
    float* T = reinterpret_cast<float*>(g_tree) + (long long)f * 72;
    float inf = __int_as_float(0x7f800000);
    T[8 + t] = (t < NBIN) ? S[t] : inf;  // padded sorted row
    if (t == 0) {
        T[0] = S[31]; T[1] = S[15]; T[2] = S[47]; T[3] = S[7];
        T[4] = S[23]; T[5] = S[39]; T[6] = S[55]; T[7] = inf;
    }
}

__global__ __launch_bounds__(256)
void hashing_discretizer_kernel(const void* __restrict__ keys_,
                                const float* __restrict__ vals,
                                const void* __restrict__ fid_,
                                float* __restrict__ out,
                                int nnz, int F) {
    int i = blockIdx.x * blockDim.x + threadIdx.x;
    if (i >= nnz) return;

    long long key;
    if (g_k64) key = ((const long long*)keys_)[i];
    else       key = (long long)((const int*)keys_)[i];
    float v = __ldg(vals + i);

    bool cal;
    int fx;
    if (g_arange) {
        cal = (unsigned long long)key < (unsigned long long)F;
        fx = (int)key;
    } else {
        // generic searchsorted(feature_ids, key, 'left')
        int lo = 0, hi = F;
        if (g_f64) {
            const long long* fid = (const long long*)fid_;
            while (lo < hi) {
                int mid = (lo + hi) >> 1;
                if (__ldg(fid + mid) < key) lo = mid + 1; else hi = mid;
            }
            fx = min(lo, F - 1);
            cal = (__ldg(fid + fx) == key);
        } else {
            const int* fid = (const int*)fid_;
            int k32 = (int)key;
            while (lo < hi) {
                int mid = (lo + hi) >> 1;
                if (__ldg(fid + mid) < k32) lo = mid + 1; else hi = mid;
            }
            fx = min(lo, F - 1);
            cal = (__ldg(fid + fx) == k32);
        }
    }

    unsigned okey;
    float oval;
    if (cal) {
        const float4* base = g_tree + fx * 18;
        float4 t0 = __ldg(base);      // {S31, S15, S47, S7}
        float4 t1 = __ldg(base + 1);  // {S23, S39, S55, INF}
        int b0 = t0.x < v;                    // vs S31
        float k1 = b0 ? t0.z : t0.y;          // S47 : S15
        int b1 = k1 < v;
        float kA = b1 ? t1.x : t0.w;          // b0=0: S23 : S7
        float kB = b1 ? t1.z : t1.y;          // b0=1: S55 : S39
        float k2 = b0 ? kB : kA;
        int b2 = k2 < v;
        int p = (b0 << 2) | (b1 << 1) | b2;   // chunk index; bin in [8p, 8p+8]
        float4 c0 = __ldg(base + 2 + 2 * p);  // S[8p .. 8p+3]
        float4 c1 = __ldg(base + 3 + 2 * p);  // S[8p+4 .. 8p+7] (INF padded)
        int bin = (p << 3)
                + (c0.x < v) + (c0.y < v) + (c0.z < v) + (c0.w < v)
                + (c1.x < v) + (c1.y < v) + (c1.z < v) + (c1.w < v);
        unsigned h = ((unsigned)(unsigned long long)key * GOLDEN
                      + (unsigned)bin) * GOLDEN;
        okey = h & OUT_MASK;
        oval = 1.0f;
    } else {
        okey = (unsigned)(unsigned long long)key & OUT_MASK;
        oval = v;
    }

    out[i] = (float)okey;   // < 2^22, exact in f32
    out[nnz + i] = oval;
}

extern "C" void kernel_launch(void* const* d_in, const int* in_sizes, int n_in,
                              void* d_out, int out_size) {
    const void* keys  = d_in[0];
    const float* vals = (const float*)d_in[1];
    const void* fid   = d_in[2];
    const float* bins = (const float*)d_in[3];
    int nnz = in_sizes[0];
    int F   = in_sizes[2];

    detect_kernel<<<1, 256>>>((const unsigned*)keys, (const unsigned*)fid,
                              nnz, F);
    build_tree_kernel<<<F, 64>>>(bins, F);

    const int threads = 256;
    int blocks = (nnz + threads - 1) / threads;
    hashing_discretizer_kernel<<<blocks, threads>>>(keys, vals, fid,
                                                    (float*)d_out, nnz, F);
}